// round 12
// baseline (speedup 1.0000x reference)
#include <cuda_runtime.h>

#define HH 192
#define WW 192
#define BB 4
#define CC 16
#define HID 128
#define STEPS 10
#define NPIX (BB*HH*WW)          // 147456
#define TILE 16
#define XPP 578                  // x_s plane pitch; 578 % 32 == 2 -> conflict-free half-warps
#define WPITCH 34                // fc0 weight pitch (even -> 8B aligned rows)
#define NBLK1 576                // k1 grid size

typedef unsigned long long ull;

// packed f32x2 FMA: d = a*b + d (lane-wise)
__device__ __forceinline__ void ffma2(ull& d, ull a, ull b) {
    asm("fma.rn.f32x2 %0, %1, %2, %0;" : "+l"(d) : "l"(a), "l"(b));
}
__device__ __forceinline__ float unpack_sum(ull a) {
    float lo, hi;
    asm("mov.b64 {%0,%1}, %2;" : "=f"(lo), "=f"(hi) : "l"(a));
    return lo + hi;
}
__device__ __forceinline__ ull pack2(float lo, float hi) {
    ull r;
    asm("mov.b64 %0,{%1,%2};" : "=l"(r) : "f"(lo), "f"(hi));
    return r;
}

// ---------------- scratch (static device arrays; no runtime alloc) ----------
__device__ float g_x[NPIX*CC];            // working state, NHWC
__device__ float g_h[(size_t)NPIX*HID];   // hidden activations, [pix][128]
__device__ float g_part[NBLK1*256];       // per-block partials: [blk][0:128]=sum, [128:256]=sq
__device__ float g_sum[HID];
__device__ float g_sq [HID];
__device__ __align__(16) float g_wf0p[128*WPITCH]; // fc0 weights, permuted/padded
__device__ __align__(16) float g_ws2 [16*9*12];    // conv weights, zero-padded pairs

// ---------------- K0: one-time weight prep (idempotent, runs per launch) ----
__global__ void __launch_bounds__(256) k0(const float* __restrict__ wp,
                                          const float* __restrict__ wf0)
{
    const int t = threadIdx.x;
    // conv weights as zero-padded rows: (c,ky) -> [w0..w8, 0, pad(0), pad(0)]
    for (int i = t; i < 16*9*12; i += 256) {
        int j = i % 12, row = i / 12;
        g_ws2[row*12 + j] = (j < 9) ? wp[row*9 + j] : 0.f;
    }
    // fc0 weights, permuted to interleaved {x,conv} order; pad slots zeroed
    for (int i = t; i < 128*WPITCH; i += 256) {
        int o = i / WPITCH, jp = i % WPITCH;
        float v = 0.f;
        if (jp < 32) {
            int j = (jp & 1) ? (16 + (jp >> 1)) : (jp >> 1);   // inverse of jp(j)
            v = wf0[o*32 + j];
        }
        g_wf0p[o*WPITCH + jp] = v;
    }
}

// ---------------- K1: depthwise conv + fc0 + partial BN stats ---------------
// grid: 576 blocks (4 batches * 12*12 tiles of 16x16), 256 threads
extern __shared__ __align__(16) float smem[];
__global__ void __launch_bounds__(256, 2) k1(const float* __restrict__ xsrc,
                                             const float* __restrict__ bp,
                                             const float* __restrict__ bf0)
{
    float* s_ins = smem;                 // [256 pix][32 interleaved ch]   8192
    float* s_x   = s_ins + 256*32;       // [16][578]                      9248
    float* s_wf0 = s_x   + 16*XPP;       // [128][34] permuted-interleaved 4352
    float* s_ws2 = s_wf0 + 128*WPITCH;   // [16][9][12] paired conv w      1728
    float* s_bp  = s_ws2 + 16*9*12;      // 16
    float* s_bf0 = s_bp  + 16;           // 128
    float* s_red = s_bf0 + 128;          // 512

    const int t   = threadIdx.x;
    const int blk = blockIdx.x;
    const int b   = blk / 144;
    const int tb  = blk % 144;
    const int y0  = (tb / 12) * TILE;
    const int x0  = (tb % 12) * TILE;

    // vectorized copy of pre-permuted weights (flat float4; bases 16B-aligned)
    for (int i = t; i < 128*WPITCH/4; i += 256)
        ((float4*)s_wf0)[i] = ((const float4*)g_wf0p)[i];
    for (int i = t; i < 16*9*12/4; i += 256)
        ((float4*)s_ws2)[i] = ((const float4*)g_ws2)[i];
    if (t < 16)  s_bp[t]  = bp[t];
    if (t < 128) s_bf0[t] = bf0[t];

    // 24x24 halo with reflect padding, [c][ty][tx] planes
    for (int i = t; i < 16*24*24; i += 256) {
        int c  = i & 15;
        int r  = i >> 4;
        int tx = r % 24, ty = r / 24;
        int gy = y0 - 4 + ty; gy = gy < 0 ? -gy : (gy >= HH ? 2*HH-2-gy : gy);
        int gx = x0 - 4 + tx; gx = gx < 0 ? -gx : (gx >= WW ? 2*WW-2-gx : gx);
        s_x[c*XPP + ty*24 + tx] = xsrc[((b*HH + gy)*WW + gx)*CC + c];
    }
    __syncthreads();

    // ---- phase 1: depthwise conv, row-sliding, f32x2 ----
    // thread = (c = t&15, slot = t>>4); computes rows 0..15 of column slot
    {
        const int c = t & 15, slot = t >> 4;
        ull acc2[16];
        #pragma unroll
        for (int i = 0; i < 16; i++) acc2[i] = 0ull;
        const float* xs  = s_x + c*XPP + slot;
        const float* wb_ = s_ws2 + c*9*12;

        #pragma unroll
        for (int r = 0; r < 24; r++) {
            float v[9];
            #pragma unroll
            for (int j = 0; j < 9; j++) v[j] = xs[r*24 + j];
            ull v2[5];
            #pragma unroll
            for (int k = 0; k < 4; k++) v2[k] = pack2(v[2*k], v[2*k+1]);
            v2[4] = pack2(v[8], 0.f);
            #pragma unroll
            for (int ky = 0; ky < 9; ky++) {
                int i = r - ky;
                if (i >= 0 && i < 16) {          // compile-time after unroll
                    const float* wk = wb_ + ky*12;
                    ulonglong2 wa  = *(const ulonglong2*)wk;
                    ulonglong2 wbv = *(const ulonglong2*)(wk + 4);
                    ull wcl = *(const ull*)(wk + 8);
                    ffma2(acc2[i], wa.x,  v2[0]);
                    ffma2(acc2[i], wa.y,  v2[1]);
                    ffma2(acc2[i], wbv.x, v2[2]);
                    ffma2(acc2[i], wbv.y, v2[3]);
                    ffma2(acc2[i], wcl,   v2[4]);
                }
            }
        }
        // epilogue: one STS.64 per row, interleaved {x, conv}
        const float bc = s_bp[c];
        #pragma unroll
        for (int i = 0; i < 16; i++) {
            float cv = bc + unpack_sum(acc2[i]);
            float xv = xs[(i+4)*24 + 4];
            int p = i*16 + slot;
            *(ull*)(s_ins + p*32 + 2*c) = pack2(xv, cv);
        }
    }
    __syncthreads();

    // ---- phase 2: fc0, 2 output channels per thread, f32x2 ----
    {
        const int o0 = t & 63, q = t >> 6;
        ull wA[16], wB[16];
        const ull* wra = (const ull*)(s_wf0 + o0*WPITCH);
        const ull* wrb = (const ull*)(s_wf0 + (o0+64)*WPITCH);
        #pragma unroll
        for (int k = 0; k < 16; k++) { wA[k] = wra[k]; wB[k] = wrb[k]; }
        const float bA = s_bf0[o0], bB = s_bf0[o0+64];
        float sumA = 0.f, sqA = 0.f, sumB = 0.f, sqB = 0.f;

        for (int ii = 0; ii < 64; ii++) {
            int p = ii*4 + q;
            const ulonglong2* inp = (const ulonglong2*)(s_ins + p*32);
            ull a0 = 0ull, a1 = 0ull, b0 = 0ull, b1 = 0ull;
            #pragma unroll
            for (int k = 0; k < 8; k++) {
                ulonglong2 v = inp[k];
                ffma2(a0, wA[2*k],   v.x);
                ffma2(a1, wA[2*k+1], v.y);
                ffma2(b0, wB[2*k],   v.x);
                ffma2(b1, wB[2*k+1], v.y);
            }
            float hA = bA + unpack_sum(a0) + unpack_sum(a1);
            float hB = bB + unpack_sum(b0) + unpack_sum(b1);
            int py = p >> 4, px = p & 15;
            int gp = (b*HH + y0 + py)*WW + x0 + px;
            g_h[(size_t)gp*128 + o0]      = hA;
            g_h[(size_t)gp*128 + o0 + 64] = hB;
            sumA += hA; sqA = fmaf(hA, hA, sqA);
            sumB += hB; sqB = fmaf(hB, hB, sqB);
        }
        s_red[t] = sumA; s_red[256 + t] = sumB;
        __syncthreads();
        if (t < 128) {
            int oo = t & 63;
            int base = (t < 64) ? 0 : 256;
            g_part[blk*256 + t] = s_red[base+oo] + s_red[base+64+oo]
                                + s_red[base+128+oo] + s_red[base+192+oo];
        }
        __syncthreads();
        s_red[t] = sqA; s_red[256 + t] = sqB;
        __syncthreads();
        if (t < 128) {
            int oo = t & 63;
            int base = (t < 64) ? 0 : 256;
            g_part[blk*256 + 128 + t] = s_red[base+oo] + s_red[base+64+oo]
                                      + s_red[base+128+oo] + s_red[base+192+oo];
        }
    }
}

// ---------------- K2: deterministic reduce of per-block partials ------------
__global__ void __launch_bounds__(256) k2()
{
    __shared__ float red[256];
    const int c = blockIdx.x;
    const int t = threadIdx.x;
    float s = 0.f, q = 0.f;
    for (int i = t; i < NBLK1; i += 256) {
        s += g_part[i*256 + c];
        q += g_part[i*256 + 128 + c];
    }
    red[t] = s;
    __syncthreads();
    for (int st = 128; st > 0; st >>= 1) {
        if (t < st) red[t] += red[t + st];
        __syncthreads();
    }
    if (t == 0) g_sum[c] = red[0];
    __syncthreads();
    red[t] = q;
    __syncthreads();
    for (int st = 128; st > 0; st >>= 1) {
        if (t < st) red[t] += red[t + st];
        __syncthreads();
    }
    if (t == 0) g_sq[c] = red[0];
}

// ---------------- K3: BN finalize + ReLU + fc1 + masked update --------------
// grid: NPIX/64 = 2304 blocks, 256 threads; 64 consecutive pixels per block
__global__ void __launch_bounds__(256) k3(const float* __restrict__ xsrc,
                                          float* __restrict__ xdst,
                                          const float* __restrict__ u,
                                          const float* __restrict__ wf1,
                                          const float* __restrict__ gamma,
                                          const float* __restrict__ beta,
                                          int step)
{
    __shared__ __align__(16) float s_h [64*132];   // pitch 132: conflict-free f32x2 reads
    __shared__ __align__(16) float s_w1[16*132];   // [co][128] padded
    __shared__ float s_sc[128], s_sh[128];
    __shared__ __align__(16) float s_d [64*16];

    const int t = threadIdx.x;
    const long pg0 = (long)blockIdx.x * 64;

    if (t < 128) {
        float mean = g_sum[t] * (1.0f/NPIX);
        float var  = g_sq [t] * (1.0f/NPIX) - mean*mean;
        float rs   = rsqrtf(var + 1e-5f);
        float sc   = gamma[t] * rs;
        s_sc[t] = sc;
        s_sh[t] = beta[t] - mean*sc;
    }
    for (int i = t; i < 16*128; i += 256) s_w1[(i>>7)*132 + (i&127)] = wf1[i];
    __syncthreads();

    // normalize + relu while staging h
    const float* hp = g_h + (size_t)pg0*128;
    for (int i = 0; i < 32; i++) {
        int idx = i*256 + t;
        int p = idx >> 7, o = idx & 127;
        s_h[p*132 + o] = fmaxf(fmaf(hp[idx], s_sc[o], s_sh[o]), 0.f);
    }
    __syncthreads();

    // fc1 via packed f32x2: thread = (co = t&15, slot = t>>4), 4 pixels per thread
    // FULL 128-channel reduction: 32 ulonglong2 (4 floats) per pixel
    {
        const int co = t & 15, slot = t >> 4;
        const ulonglong2* w4 = (const ulonglong2*)(s_w1 + co*132);
        #pragma unroll
        for (int i = 0; i < 4; i++) {
            int p = slot + 16*i;
            const ulonglong2* h4 = (const ulonglong2*)(s_h + p*132);
            ull accA = 0ull, accB = 0ull;
            #pragma unroll
            for (int k = 0; k < 32; k++) {
                ulonglong2 hv = h4[k], wv = w4[k];
                ffma2(accA, wv.x, hv.x);
                ffma2(accB, wv.y, hv.y);
            }
            s_d[p*16 + co] = unpack_sum(accA) + unpack_sum(accB);
        }
    }
    __syncthreads();

    // masked residual update, float4 NHWC, channel 0 frozen
    {
        const int p = t >> 2, q = t & 3;
        const long pg = pg0 + p;
        int xc  = (int)(pg % (long)WW);
        int rem = (int)(pg / WW);
        int y = rem % HH;
        int b = rem / HH;
        float uv = u[((step*BB + b)*HH + y)*WW + xc];
        float m = uv > 0.5f ? 1.f : 0.f;
        float4 xo = ((const float4*)xsrc)[pg*4 + q];
        float4 dd = ((const float4*)s_d)[p*4 + q];
        float4 out;
        out.x = fmaf(dd.x, m, xo.x);
        out.y = fmaf(dd.y, m, xo.y);
        out.z = fmaf(dd.z, m, xo.z);
        out.w = fmaf(dd.w, m, xo.w);
        if (q == 0) out.x = xo.x;   // frozen input channel
        ((float4*)xdst)[pg*4 + q] = out;
    }
}

// ---------------- launch --------------------------------------------------
extern "C" void kernel_launch(void* const* d_in, const int* in_sizes, int n_in,
                              void* d_out, int out_size)
{
    const float* x     = (const float*)d_in[0];
    const float* ru    = (const float*)d_in[1];
    const float* wp    = (const float*)d_in[2];
    const float* bp    = (const float*)d_in[3];
    const float* wf0   = (const float*)d_in[4];
    const float* bf0   = (const float*)d_in[5];
    const float* wf1   = (const float*)d_in[6];
    const float* gamma = (const float*)d_in[7];
    const float* beta  = (const float*)d_in[8];

    static const size_t k1_smem = (256*32 + 16*XPP + 128*WPITCH + 16*9*12 + 16 + 128 + 512) * sizeof(float);
    cudaFuncSetAttribute(k1, cudaFuncAttributeMaxDynamicSharedMemorySize, (int)k1_smem);

    float* gx;
    cudaGetSymbolAddress((void**)&gx, g_x);

    k0<<<1, 256>>>(wp, wf0);
    for (int s = 0; s < STEPS; s++) {
        const float* xin  = (s == 0)        ? x              : gx;
        float*       xout = (s == STEPS-1)  ? (float*)d_out  : gx;
        k1<<<NBLK1, 256, k1_smem>>>(xin, bp, bf0);
        k2<<<128, 256>>>();
        k3<<<NPIX/64, 256>>>(xin, xout, ru, wf1, gamma, beta, s);
    }
}